// round 2
// baseline (speedup 1.0000x reference)
#include <cuda_runtime.h>
#include <cuda_bf16.h>
#include <math.h>

#define BB 2
#define TT 4
#define CMAP 20
#define LOCN 480
#define GLON 960
#define LL (LOCN*LOCN)          // 230400
#define GG (GLON*GLON)          // 921600
#define NSEM 16
#define PH 120
#define PW 160
#define NPTS (PH*PW)            // 19200
#define VRN 100
#define ZBN 80
#define DEGF 57.29577951308232f

static const long long FE_OFF   = 0LL;
static const long long LMAP_OFF = 44236800LL;
static const long long GMAP_OFF = 53452800LL;
static const long long LP_OFF   = 90316800LL;
static const long long GP_OFF   = 90316824LL;
static const long long LB_OFF   = 90316848LL;
static const long long OG_OFF   = 90316880LL;

struct St {
    float lpose[BB][3], gpose[BB][3], orig[BB][3];
    int   lmb[BB][4];
    float ct[BB], snt[BB], stx[BB], sty[BB];
    int   xg[BB], yg[BB];
    int   wr0[BB], wc0[BB], nr0[BB], nc0[BB];
    int   updg[BB];
    int   doneF[BB*TT], updgF[BB*TT];
};
__device__ St g_st;

__device__ __align__(16) float g_vox0[BB][VRN*VRN*ZBN];        // ch0, full z
__device__ __align__(16) float g_voxS[BB][NSEM][VRN*VRN*12];   // sem, z in [13,25)
__device__ __align__(16) float g_semP[BB][NPTS][NSEM];         // pooled seg
__device__ __align__(16) float g_avwin[BB][18][VRN*VRN];       // av window (ch 0,1,4..19)
__device__ __align__(16) float g_rot[BB][18][LL];              // rotated
__device__ __align__(16) float g_cur0[BB][LL];                 // pre-dilation ch0

// ---------------- init: pose state + bool-flag decoding ----------------
__device__ static void decode_flags(const void* p, int* outF) {
    const float* pf = (const float*)p;
    const int* pi = (const int*)p;
    const unsigned char* pb = (const unsigned char*)p;
    bool fok = true, iok = true;
    for (int k = 0; k < BB*TT; k++) {
        float v = pf[k]; if (!(v == 0.0f || v == 1.0f)) fok = false;
        int w = pi[k];   if (w != 0 && w != 1) iok = false;
    }
    for (int k = 0; k < BB*TT; k++)
        outF[k] = fok ? (pf[k] != 0.0f) : (iok ? (pi[k] != 0) : (pb[k] != 0));
}

__global__ void k_init(const float* ilp, const float* igp, const int* ilmb, const float* iog,
                       const void* dn, const void* ug) {
    if (threadIdx.x || blockIdx.x) return;
    for (int b = 0; b < BB; b++) {
        for (int k = 0; k < 3; k++) {
            g_st.lpose[b][k] = ilp[b*3+k];
            g_st.gpose[b][k] = igp[b*3+k];
            g_st.orig[b][k]  = iog[b*3+k];
        }
        for (int k = 0; k < 4; k++) g_st.lmb[b][k] = ilmb[b*4+k];
    }
    decode_flags(dn, g_st.doneF);
    decode_flags(ug, g_st.updgF);
}

// ---------------- per-step: zero maps on done ----------------
__global__ __launch_bounds__(256) void k_reset(float* out, int t) {
    int b = blockIdx.y;
    if (!g_st.doneF[b*TT + t]) return;
    long long i = (long long)blockIdx.x * 256 + threadIdx.x;  // 5,760,000 float4 per batch
    float4 z = make_float4(0.f, 0.f, 0.f, 0.f);
    const long long LM4 = (long long)CMAP * LL / 4;   // 1,152,000
    if (i < LM4) {
        ((float4*)(out + LMAP_OFF + (long long)b * CMAP * LL))[i] = z;
    } else {
        i -= LM4;
        ((float4*)(out + GMAP_OFF + (long long)b * CMAP * GG))[i] = z;
    }
}

// ---------------- per-step: all pose math (single thread) ----------------
__global__ void k_pose(const float* pd, float* out, int t) {
    if (threadIdx.x || blockIdx.x) return;
    for (int b = 0; b < BB; b++) {
        bool done = g_st.doneF[b*TT + t] != 0;
        bool updg = g_st.updgF[b*TT + t] != 0;
        float lx, ly, lo, gx_, gy_, go_, o0, o1, o2;
        int mOld[4];
        if (done) {
            lx = 12.f; ly = 12.f; lo = 0.f;
            gx_ = 24.f; gy_ = 24.f; go_ = 0.f;
            o0 = 12.f; o1 = 12.f; o2 = 0.f;
            mOld[0] = 240; mOld[1] = 720; mOld[2] = 240; mOld[3] = 720;
        } else {
            lx = g_st.lpose[b][0]; ly = g_st.lpose[b][1]; lo = g_st.lpose[b][2];
            gx_ = g_st.gpose[b][0]; gy_ = g_st.gpose[b][1]; go_ = g_st.gpose[b][2];
            o0 = g_st.orig[b][0]; o1 = g_st.orig[b][1]; o2 = g_st.orig[b][2];
            for (int k = 0; k < 4; k++) mOld[k] = g_st.lmb[b][k];
        }

        // get_new_pose
        float rx = pd[(b*TT+t)*3+0], ry = pd[(b*TT+t)*3+1], ro = pd[(b*TT+t)*3+2];
        float s = sinf(lo / DEGF), c = cosf(lo / DEGF);
        float px = lx + rx*c - ry*s;
        float py = ly + rx*s + ry*c;
        float po = lo + ro*DEGF;
        po = fmodf(po - 180.0f, 360.0f) + 180.0f;
        po = fmodf(po + 180.0f, 360.0f) - 180.0f;

        // spatial-transform params
        float th = (90.0f - po) * (float)(M_PI / 180.0);
        g_st.ct[b]  = cosf(th);
        g_st.snt[b] = sinf(th);
        float ax = px * 100.0f / 5.0f;
        float ay = py * 100.0f / 5.0f;
        g_st.stx[b] = -((ax - 240.0f) / 240.0f);
        g_st.sty[b] = -((ay - 240.0f) / 240.0f);
        g_st.xg[b] = (int)ax;
        g_st.yg[b] = (int)ay;

        // update_global_env pose math
        float gnx = px + o0, gny = py + o1, gno = po + o2;
        int r  = (int)(gny * 100.0f / 5.0f);
        int cc = (int)(gnx * 100.0f / 5.0f);
        int gx1 = min(max(r  - 240, 0), GLON - LOCN);
        int gy1 = min(max(cc - 240, 0), GLON - LOCN);
        float no0 = (float)(gy1 * 5) / 100.0f;
        float no1 = (float)(gx1 * 5) / 100.0f;
        float lnx = gnx - no0, lny = gny - no1, lno = gno - 0.0f;

        g_st.wr0[b] = min(max(mOld[0], 0), GLON - LOCN);
        g_st.wc0[b] = min(max(mOld[2], 0), GLON - LOCN);
        g_st.nr0[b] = gx1;
        g_st.nc0[b] = gy1;
        g_st.updg[b] = updg ? 1 : 0;

        float* lpO = out + LP_OFF + (long long)(b*TT+t)*3;
        float* gpO = out + GP_OFF + (long long)(b*TT+t)*3;
        float* lbO = out + LB_OFF + (long long)(b*TT+t)*4;
        float* ogO = out + OG_OFF + (long long)(b*TT+t)*3;
        if (updg) {
            lpO[0]=lnx; lpO[1]=lny; lpO[2]=lno;
            gpO[0]=gnx; gpO[1]=gny; gpO[2]=gno;
            lbO[0]=(float)gx1; lbO[1]=(float)(gx1+LOCN); lbO[2]=(float)gy1; lbO[3]=(float)(gy1+LOCN);
            ogO[0]=no0; ogO[1]=no1; ogO[2]=0.0f;
            g_st.lpose[b][0]=lnx; g_st.lpose[b][1]=lny; g_st.lpose[b][2]=lno;
            g_st.gpose[b][0]=gnx; g_st.gpose[b][1]=gny; g_st.gpose[b][2]=gno;
            g_st.lmb[b][0]=gx1; g_st.lmb[b][1]=gx1+LOCN; g_st.lmb[b][2]=gy1; g_st.lmb[b][3]=gy1+LOCN;
            g_st.orig[b][0]=no0; g_st.orig[b][1]=no1; g_st.orig[b][2]=0.0f;
        } else {
            lpO[0]=px; lpO[1]=py; lpO[2]=po;
            gpO[0]=gx_; gpO[1]=gy_; gpO[2]=go_;
            lbO[0]=(float)mOld[0]; lbO[1]=(float)mOld[1]; lbO[2]=(float)mOld[2]; lbO[3]=(float)mOld[3];
            ogO[0]=o0; ogO[1]=o1; ogO[2]=o2;
            g_st.lpose[b][0]=px; g_st.lpose[b][1]=py; g_st.lpose[b][2]=po;
            g_st.gpose[b][0]=gx_; g_st.gpose[b][1]=gy_; g_st.gpose[b][2]=go_;
            for (int k=0;k<4;k++) g_st.lmb[b][k]=mOld[k];
            g_st.orig[b][0]=o0; g_st.orig[b][1]=o1; g_st.orig[b][2]=o2;
        }
    }
}

// ---------------- zero voxel scratch ----------------
__global__ __launch_bounds__(256) void k_zvox() {
    long long i = (long long)blockIdx.x * 256 + threadIdx.x;
    const long long n0 = (long long)BB * VRN * VRN * ZBN / 4;       // 400,000
    const long long n1 = (long long)BB * NSEM * VRN * VRN * 12 / 4; // 960,000
    float4 z = make_float4(0.f, 0.f, 0.f, 0.f);
    if (i < n0) ((float4*)g_vox0)[i] = z;
    else if (i < n0 + n1) ((float4*)g_voxS)[i - n0] = z;
}

// ---------------- 4x4 avg pool of seg channels ----------------
__global__ __launch_bounds__(256) void k_pool(const float* obs, int t) {
    int idx = blockIdx.x * 256 + threadIdx.x;     // BB*NSEM*NPTS = 614,400 exact
    int j = idx % PW;
    int i = (idx / PW) % PH;
    int c = (idx / NPTS) % NSEM;
    int b = idx / (NPTS * NSEM);
    const float* p = obs + ((long long)(b*TT + t) * CMAP + 4 + c) * (long long)(480*640)
                     + (long long)(4*i) * 640 + 4*j;
    float s = 0.f;
    #pragma unroll
    for (int dy = 0; dy < 4; dy++)
        #pragma unroll
        for (int dx = 0; dx < 4; dx++)
            s += p[dy*640 + dx];
    g_semP[b][i*PW + j][c] = s * (1.0f/16.0f);
}

// ---------------- trilinear voxel splat ----------------
__global__ __launch_bounds__(256) void k_splat(const float* obs, float focal, int t) {
    int idx = blockIdx.x * 256 + threadIdx.x;     // BB*NPTS*8 = 307,200 exact
    int corner = idx & 7;
    int pt = (idx >> 3) % NPTS;
    int b = idx / (NPTS * 8);
    int i = pt / PW, j = pt % PW;
    float d = obs[((long long)(b*TT + t) * CMAP + 3) * (long long)(480*640)
                  + (long long)(4*i) * 640 + 4*j];
    if (!(d > 50.0f && d < 350.0f)) return;
    float X = (((float)(4*j) - 319.5f) * d) / focal;       X = X + 250.0f;
    float Z = (((float)(479 - 4*i) - 239.5f) * d) / focal; Z = Z + 88.0f;
    float cx = ((X / 5.0f - 50.0f) / 100.0f) * 2.0f;
    float cy = ((d / 5.0f - 50.0f) / 100.0f) * 2.0f;
    float cz = ((Z / 5.0f - 32.0f) / 80.0f) * 2.0f;
    float pxp = cx * 100.0f / 2.0f + 50.0f;
    float pyp = cy * 100.0f / 2.0f + 50.0f;
    float pzp = cz * 80.0f / 2.0f + 40.0f;
    float f0 = floorf(pxp), f1 = floorf(pyp), f2 = floorf(pzp);
    float p0 = f0 + (float)(corner & 1);
    float p1 = f1 + (float)((corner >> 1) & 1);
    float p2 = f2 + (float)((corner >> 2) & 1);
    float w = 1.0f;
    w = w * (1.0f - fabsf(pxp - p0)); if (!(p0 > 0.0f && p0 < 100.0f)) w = 0.0f;
    w = w * (1.0f - fabsf(pyp - p1)); if (!(p1 > 0.0f && p1 < 100.0f)) w = 0.0f;
    w = w * (1.0f - fabsf(pzp - p2)); if (!(p2 > 0.0f && p2 <  80.0f)) w = 0.0f;
    if (w == 0.0f) return;
    int ix = (int)p0, iy = (int)p1, iz = (int)p2;
    atomicAdd(&g_vox0[b][(ix*VRN + iy)*ZBN + iz], w);
    if (iz >= 13 && iz < 25) {
        const float* sp = g_semP[b][pt];
        int zo = iz - 13;
        #pragma unroll
        for (int c = 0; c < NSEM; c++) {
            float v = sp[c];
            if (v != 0.0f) atomicAdd(&g_voxS[b][c][(ix*VRN + iy)*12 + zo], v * w);
        }
    }
}

// ---------------- heights: round voxels, sum z, clip -> av window ----------------
__global__ __launch_bounds__(256) void k_heights() {
    int idx = blockIdx.x * 256 + threadIdx.x;
    if (idx >= BB * VRN * VRN) return;
    int xy = idx % (VRN * VRN);
    int b = idx / (VRN * VRN);
    const float* v0 = &g_vox0[b][xy * ZBN];
    float all0 = 0.f, ag0 = 0.f;
    for (int z = 0; z < ZBN; z++) {
        float r = rintf(v0[z]);
        all0 += r;
        if (z >= 13 && z < 25) ag0 += r;
    }
    g_avwin[b][0][xy] = fminf(fmaxf(ag0 / 1.0f, 0.0f), 1.0f);
    g_avwin[b][1][xy] = fminf(fmaxf(all0 / 1.0f, 0.0f), 1.0f);
    for (int c = 0; c < NSEM; c++) {
        const float* vs = &g_voxS[b][c][xy * 12];
        float sm = 0.f;
        #pragma unroll
        for (int z = 0; z < 12; z++) sm += rintf(vs[z]);
        g_avwin[b][2 + c][xy] = fminf(fmaxf(sm / 5.0f, 0.0f), 1.0f);
    }
}

// ---------------- rotation resample (18 nonzero channels) ----------------
__global__ __launch_bounds__(256) void k_rotate() {
    int b = blockIdx.y;
    int ij = blockIdx.x * 256 + threadIdx.x;      // 230,400 exact
    int i = ij / LOCN, j = ij % LOCN;
    const float step = 2.0f / 479.0f;
    float gx = -1.0f + (float)j * step;
    float gy = -1.0f + (float)i * step;
    float ct = g_st.ct[b], sn = g_st.snt[b];
    float gX = ct * gx + (-sn) * gy;
    float gY = sn * gx + ct * gy;
    float x = ((gX + 1.0f) * 479.0f) / 2.0f;
    float y = ((gY + 1.0f) * 479.0f) / 2.0f;
    float x0 = floorf(x), y0 = floorf(y);
    float acc[18];
    #pragma unroll
    for (int s = 0; s < 18; s++) acc[s] = 0.0f;
    #pragma unroll
    for (int k = 0; k < 4; k++) {
        float xi = x0 + (float)(k & 1);
        float yi = y0 + (float)(k >> 1);
        if (!(xi >= 0.0f && xi <= 479.0f && yi >= 0.0f && yi <= 479.0f)) continue;
        int xii = (int)xi, yii = (int)yi;
        if (yii < 240 || yii > 339 || xii < 190 || xii > 289) continue;  // av==0 outside window
        float wg = (1.0f - fabsf(x - xi)) * (1.0f - fabsf(y - yi));
        int widx = (yii - 240) * VRN + (xii - 190);
        #pragma unroll
        for (int s = 0; s < 18; s++) acc[s] += g_avwin[b][s][widx] * wg;
    }
    #pragma unroll
    for (int s = 0; s < 18; s++) g_rot[b][s][ij] = acc[s];
}

// ---------------- translate resample + max-fuse + markers ----------------
__global__ __launch_bounds__(256) void k_translate(float* out) {
    int b = blockIdx.y;
    int ij = blockIdx.x * 256 + threadIdx.x;
    int i = ij / LOCN, j = ij % LOCN;
    const float step = 2.0f / 479.0f;
    float gx = (-1.0f + (float)j * step) + g_st.stx[b];
    float gy = (-1.0f + (float)i * step) + g_st.sty[b];
    float x = ((gx + 1.0f) * 479.0f) / 2.0f;
    float y = ((gy + 1.0f) * 479.0f) / 2.0f;
    float x0 = floorf(x), y0 = floorf(y);
    float tr[18];
    #pragma unroll
    for (int s = 0; s < 18; s++) tr[s] = 0.0f;
    #pragma unroll
    for (int k = 0; k < 4; k++) {
        float xi = x0 + (float)(k & 1);
        float yi = y0 + (float)(k >> 1);
        if (!(xi >= 0.0f && xi <= 479.0f && yi >= 0.0f && yi <= 479.0f)) continue;
        float wg = (1.0f - fabsf(x - xi)) * (1.0f - fabsf(y - yi));
        int a = (int)yi * LOCN + (int)xi;
        #pragma unroll
        for (int s = 0; s < 18; s++) tr[s] += g_rot[b][s][a] * wg;
    }
    float* lm = out + LMAP_OFF + (long long)b * CMAP * LL + ij;
    g_cur0[b][ij] = fmaxf(lm[0], tr[0]);                       // ch0 -> pre-dilation buffer
    lm[(long long)1 * LL] = fmaxf(lm[(long long)1 * LL], tr[1]);
    int dr = i - g_st.yg[b];
    int dc = j - g_st.xg[b];
    lm[(long long)2 * LL] = (abs(dr) <= 2 && abs(dc) <= 2) ? 1.0f : 0.0f;
    float disk = ((dr*dr + dc*dc) <= 1600) ? 1.0f : 0.0f;
    lm[(long long)3 * LL] = fmaxf(lm[(long long)3 * LL], disk);
    #pragma unroll
    for (int c = 4; c < CMAP; c++)
        lm[(long long)c * LL] = fmaxf(lm[(long long)c * LL], tr[c - 2]);
}

// ---------------- 3x3 dilation of ch0 ----------------
__global__ __launch_bounds__(256) void k_dilate(float* out) {
    int b = blockIdx.y;
    int ij = blockIdx.x * 256 + threadIdx.x;
    int i = ij / LOCN, j = ij % LOCN;
    float s = 0.f;
    #pragma unroll
    for (int di = -1; di <= 1; di++) {
        int ii = i + di;
        if (ii < 0 || ii >= LOCN) continue;
        #pragma unroll
        for (int dj = -1; dj <= 1; dj++) {
            int jj = j + dj;
            if (jj < 0 || jj >= LOCN) continue;
            s += g_cur0[b][ii * LOCN + jj];
        }
    }
    out[LMAP_OFF + (long long)b * CMAP * LL + ij] = (s > 0.5f) ? 1.0f : 0.0f;
}

// ---------------- write lmap slice into gmap (guarded by updg) ----------------
__global__ __launch_bounds__(256) void k_gup(float* out) {
    int b = blockIdx.z, c = blockIdx.y;
    if (!g_st.updg[b]) return;
    int ij = blockIdx.x * 256 + threadIdx.x;
    int i = ij / LOCN, j = ij % LOCN;
    long long gidx = GMAP_OFF + ((long long)(b * CMAP + c) * GLON + (g_st.wr0[b] + i)) * GLON
                     + (g_st.wc0[b] + j);
    out[gidx] = out[LMAP_OFF + (long long)(b * CMAP + c) * LL + ij];
}

// ---------------- reslice lmap from gmap + gdown maxpool + feats write ----------------
__global__ __launch_bounds__(256) void k_feats(float* out, int t) {
    int b = blockIdx.y;
    int ij = blockIdx.x * 256 + threadIdx.x;
    int i = ij / LOCN, j = ij % LOCN;
    bool u = g_st.updg[b] != 0;
    int r0 = g_st.nr0[b], c0 = g_st.nc0[b];
    const float* gm = out + GMAP_OFF + (long long)b * CMAP * GG;
    float* lm = out + LMAP_OFF + (long long)b * CMAP * LL;
    float lv[CMAP];
    #pragma unroll
    for (int c = 0; c < CMAP; c++) {
        if (u) {
            float v = gm[(long long)c * GG + (long long)(r0 + i) * GLON + (c0 + j)];
            lm[(long long)c * LL + ij] = v;
            lv[c] = v;
        } else {
            lv[c] = lm[(long long)c * LL + ij];
        }
    }
    float gd[4];
    #pragma unroll
    for (int c = 0; c < 4; c++) {
        const float* gb = gm + (long long)c * GG + (long long)(2*i) * GLON + 2*j;
        gd[c] = fmaxf(fmaxf(gb[0], gb[1]), fmaxf(gb[GLON], gb[GLON + 1]));
    }
    float* fe = out + FE_OFF + (long long)(b*TT + t) * 24 * LL + ij;
    fe[0] = lv[0];
    fe[(long long)1*LL] = lv[1];
    fe[(long long)2*LL] = lv[2];
    fe[(long long)3*LL] = lv[3];
    #pragma unroll
    for (int c = 0; c < 4; c++) fe[(long long)(4 + c) * LL] = gd[c];
    #pragma unroll
    for (int c = 0; c < NSEM; c++) fe[(long long)(8 + c) * LL] = lv[4 + c];
}

// ---------------- launcher ----------------
extern "C" void kernel_launch(void* const* d_in, const int* in_sizes, int n_in,
                              void* d_out, int out_size) {
    const float* obs  = (const float*)d_in[0];
    const float* pd   = (const float*)d_in[1];
    const void*  dn   = d_in[2];
    const void*  ug   = d_in[3];
    // d_in[4]: seq_camera_poses (unused by reference)
    const float* ilm  = (const float*)d_in[5];
    const float* igm  = (const float*)d_in[6];
    const float* ilp  = (const float*)d_in[7];
    const float* igp  = (const float*)d_in[8];
    const int*   ilmb = (const int*)d_in[9];
    const float* iog  = (const float*)d_in[10];
    float* out = (float*)d_out;
    float focal = (float)(320.0 / tan(39.5 * M_PI / 180.0));

    cudaMemcpyAsync(out + LMAP_OFF, ilm, (size_t)BB * CMAP * LL * sizeof(float),
                    cudaMemcpyDeviceToDevice);
    cudaMemcpyAsync(out + GMAP_OFF, igm, (size_t)BB * CMAP * GG * sizeof(float),
                    cudaMemcpyDeviceToDevice);
    k_init<<<1, 1>>>(ilp, igp, ilmb, iog, dn, ug);

    for (int t = 0; t < TT; t++) {
        k_reset<<<dim3(22500, BB), 256>>>(out, t);
        k_pose<<<1, 1>>>(pd, out, t);
        k_zvox<<<5313, 256>>>();
        k_pool<<<2400, 256>>>(obs, t);
        k_splat<<<1200, 256>>>(obs, focal, t);
        k_heights<<<79, 256>>>();
        k_rotate<<<dim3(900, BB), 256>>>();
        k_translate<<<dim3(900, BB), 256>>>(out);
        k_dilate<<<dim3(900, BB), 256>>>(out);
        k_gup<<<dim3(900, CMAP, BB), 256>>>(out);
        k_feats<<<dim3(900, BB), 256>>>(out, t);
    }
}